// round 4
// baseline (speedup 1.0000x reference)
#include <cuda_runtime.h>

// LSTM: H=51, INPUT=1, OUTPUT=1, BATCH=4096, SEQ=999, future=0.
// Round 4: K-split x2. Each thread owns HALF of the 4 gate rows of W_hh
// (4 x 13 f32x2 pairs = 104 regs), lane pairs (2i, 2i+1) combine via one
// shfl_xor per gate. CTA = 1 batch element, 128 threads, forced 4 CTAs/SM
// (16 warps, 4 independent CTAs per SMSP) to hide the per-step serial chain.

#define H      51
#define SEQ    999
#define BATCH  4096
#define TPB    128
#define PH     13          // f32x2 pairs per half (half covers 26 columns)

typedef unsigned long long ull;

__device__ __forceinline__ ull fma2(ull a, ull b, ull c) {
    ull d;
    asm("fma.rn.f32x2 %0, %1, %2, %3;" : "=l"(d) : "l"(a), "l"(b), "l"(c));
    return d;
}
__device__ __forceinline__ ull pk2(float x, float y) {
    ull r;
    asm("mov.b64 %0, {%1, %2};" : "=l"(r) : "f"(x), "f"(y));
    return r;
}
__device__ __forceinline__ float2 unpk(ull v) {
    float2 r;
    asm("mov.b64 {%0, %1}, %2;" : "=f"(r.x), "=f"(r.y) : "l"(v));
    return r;
}
// sigmoid via MUFU.EX2 + MUFU.RCP (abs err ~1e-6)
__device__ __forceinline__ float sigf(float x) {
    float e = __expf(-x);
    return __fdividef(1.0f, 1.0f + e);
}
// numerically safe fast tanh
__device__ __forceinline__ float tanh_fast(float x) {
    float t = __expf(-2.0f * fabsf(x));
    float r = __fdividef(1.0f - t, 1.0f + t);
    return copysignf(r, x);
}

__global__ void __launch_bounds__(TPB, 4)
lstm_kernel(const float* __restrict__ x,     // (B, SEQ, 1)
            const float* __restrict__ Wih,   // (204, 1)
            const float* __restrict__ Whh,   // (204, 51)
            const float* __restrict__ bih,   // (204,)
            const float* __restrict__ bhh,   // (204,)
            const float* __restrict__ Wfc,   // (1, 51)
            const float* __restrict__ bfc,   // (1,)
            float* __restrict__ out)         // (B, SEQ, 1)
{
    __shared__ ull   sh_h[2][2 * PH];   // 26 ull = 52 floats (elem 51 = pad, stays 0)
    __shared__ float sh_p[2][4];        // per-warp FC partials, double buffered

    const int tid  = threadIdx.x;
    const int k    = tid >> 1;          // hidden unit 0..63 (active < 51)
    const int half = tid & 1;           // which half of the dot product
    const int b    = blockIdx.x;
    const bool act = (k < H);

    // zero h buffers (h0 = 0, pad slot stays 0 forever)
    for (int i = tid; i < 2 * 2 * PH; i += TPB) ((ull*)sh_h)[i] = 0ull;

    // ---- per-thread weights: 4 gate rows, this thread's half (13 pairs) ----
    ull w0[PH], w1[PH], w2[PH], w3[PH];
#pragma unroll
    for (int m = 0; m < PH; m++) { w0[m] = 0; w1[m] = 0; w2[m] = 0; w3[m] = 0; }
    ull wi01 = 0, wi23 = 0, bs01 = 0, bs23 = 0;
    float wfck = 0.0f, c = 0.0f;

    if (act) {
        const float* r0 = Whh + (size_t)k * H;            // gate i
        const float* r1 = r0 + (size_t)H * H;             // gate f
        const float* r2 = r1 + (size_t)H * H;             // gate g
        const float* r3 = r2 + (size_t)H * H;             // gate o
        const int base = half * 2 * PH;                   // 0 or 26
#pragma unroll
        for (int m = 0; m < PH; m++) {
            const int e0 = base + 2 * m;
            const int e1 = e0 + 1;                        // only e1==51 is OOB
            const bool ok = (e1 < H);
            w0[m] = pk2(r0[e0], ok ? r0[e1] : 0.0f);
            w1[m] = pk2(r1[e0], ok ? r1[e1] : 0.0f);
            w2[m] = pk2(r2[e0], ok ? r2[e1] : 0.0f);
            w3[m] = pk2(r3[e0], ok ? r3[e1] : 0.0f);
        }
        bs01 = pk2(bih[k] + bhh[k],               bih[k + H] + bhh[k + H]);
        bs23 = pk2(bih[k + 2*H] + bhh[k + 2*H],   bih[k + 3*H] + bhh[k + 3*H]);
        wi01 = pk2(Wih[k],         Wih[k + H]);
        wi23 = pk2(Wih[k + 2*H],   Wih[k + 3*H]);
        wfck = Wfc[k];
    }

    const float* xrow = x   + (size_t)b * SEQ;
    float*       orow = out + (size_t)b * SEQ;
    const float  bfcv = bfc[0];

    __syncthreads();

    float xv = xrow[0];
    for (int t = 0; t < SEQ; t++) {
        const int rb = t & 1;
        const int wb = rb ^ 1;
        const float xn = (t + 1 < SEQ) ? xrow[t + 1] : 0.0f;   // prefetch

        // half dot products: 4 interleaved 13-deep fma2 chains
        const ull* hb = sh_h[rb] + half * PH;
        ull a0 = 0, a1 = 0, a2 = 0, a3 = 0;
#pragma unroll
        for (int m = 0; m < PH; m++) {
            const ull hp = hb[m];                 // broadcast LDS.64
            a0 = fma2(hp, w0[m], a0);
            a1 = fma2(hp, w1[m], a1);
            a2 = fma2(hp, w2[m], a2);
            a3 = fma2(hp, w3[m], a3);
        }
        const float2 u0 = unpk(a0), u1 = unpk(a1);
        const float2 u2 = unpk(a2), u3 = unpk(a3);
        float p0 = u0.x + u0.y, p1 = u1.x + u1.y;
        float p2 = u2.x + u2.y, p3 = u3.x + u3.y;
        // combine halves (lane ^ 1); both lanes end with the full sums
        p0 += __shfl_xor_sync(0xffffffffu, p0, 1);
        p1 += __shfl_xor_sync(0xffffffffu, p1, 1);
        p2 += __shfl_xor_sync(0xffffffffu, p2, 1);
        p3 += __shfl_xor_sync(0xffffffffu, p3, 1);

        const ull xx = pk2(xv, xv);
        const float2 pre01 = unpk(fma2(xx, wi01, bs01));
        const float2 pre23 = unpk(fma2(xx, wi23, bs23));

        const float gi = sigf(p0 + pre01.x);
        const float gf = sigf(p1 + pre01.y);
        const float gg = tanh_fast(p2 + pre23.x);
        const float go = sigf(p3 + pre23.y);
        c = fmaf(gf, c, gi * gg);
        const float h = go * tanh_fast(c);      // redundant in both lanes (identical)

        if (half == 0 && act) ((float*)sh_h[wb])[k] = h;

        // FC partial: both halves contribute h*wfck -> sum is 2x, fixed by 0.5 below.
        // Inactive k (>=51) have wfck = 0.
        float yv = h * wfck;
        yv += __shfl_xor_sync(0xffffffffu, yv, 16);
        yv += __shfl_xor_sync(0xffffffffu, yv, 8);
        yv += __shfl_xor_sync(0xffffffffu, yv, 4);
        yv += __shfl_xor_sync(0xffffffffu, yv, 2);
        yv += __shfl_xor_sync(0xffffffffu, yv, 1);
        if ((tid & 31) == 0) sh_p[wb][tid >> 5] = yv;

        __syncthreads();

        if (tid == 0) {
            const float s = (sh_p[wb][0] + sh_p[wb][1]) + (sh_p[wb][2] + sh_p[wb][3]);
            orow[t] = fmaf(s, 0.5f, bfcv);
        }
        xv = xn;
    }
}

extern "C" void kernel_launch(void* const* d_in, const int* in_sizes, int n_in,
                              void* d_out, int out_size) {
    const float* x_in = (const float*)d_in[0];
    const float* Wih  = (const float*)d_in[1];
    const float* Whh  = (const float*)d_in[2];
    const float* bih  = (const float*)d_in[3];
    const float* bhh  = (const float*)d_in[4];
    const float* Wfc  = (const float*)d_in[5];
    const float* bfc  = (const float*)d_in[6];
    // d_in[7] = future (static 0) — ignored.
    float* out = (float*)d_out;

    lstm_kernel<<<BATCH, TPB>>>(x_in, Wih, Whh, bih, bhh, Wfc, bfc, out);
    (void)in_sizes; (void)n_in; (void)out_size;
}

// round 5
// speedup vs baseline: 1.4533x; 1.4533x over previous
#include <cuda_runtime.h>

// LSTM: H=51, INPUT=1, OUTPUT=1, BATCH=4096, SEQ=999, future=0.
// Round 5: gate-split x2. Even lane owns gate rows (i,f), odd lane (g,o) of
// the same hidden unit k; each computes 2 full 51-wide dot products
// (52 fma.rn.f32x2, 104 weight regs). 2 shfl_xor hand (g,o) sums to the even
// lane, which alone runs activations / c / h. 128-thread CTA = 1 batch elem,
// 4 CTAs/SM (16 warps, independent barriers) to hide the per-step chain.

#define H      51
#define SEQ    999
#define BATCH  4096
#define TPB    128
#define NPAIR  26          // ceil(51/2) f32x2 pairs per gate row (padded)

typedef unsigned long long ull;

__device__ __forceinline__ ull fma2(ull a, ull b, ull c) {
    ull d;
    asm("fma.rn.f32x2 %0, %1, %2, %3;" : "=l"(d) : "l"(a), "l"(b), "l"(c));
    return d;
}
__device__ __forceinline__ ull pk2(float x, float y) {
    ull r;
    asm("mov.b64 %0, {%1, %2};" : "=l"(r) : "f"(x), "f"(y));
    return r;
}
__device__ __forceinline__ float2 unpk(ull v) {
    float2 r;
    asm("mov.b64 {%0, %1}, %2;" : "=f"(r.x), "=f"(r.y) : "l"(v));
    return r;
}
// sigmoid via MUFU.EX2 + MUFU.RCP (abs err ~1e-6)
__device__ __forceinline__ float sigf(float x) {
    float e = __expf(-x);
    return __fdividef(1.0f, 1.0f + e);
}
// numerically safe fast tanh
__device__ __forceinline__ float tanh_fast(float x) {
    float t = __expf(-2.0f * fabsf(x));
    float r = __fdividef(1.0f - t, 1.0f + t);
    return copysignf(r, x);
}

__global__ void __launch_bounds__(TPB, 4)
lstm_kernel(const float* __restrict__ x,     // (B, SEQ, 1)
            const float* __restrict__ Wih,   // (204, 1)
            const float* __restrict__ Whh,   // (204, 51)
            const float* __restrict__ bih,   // (204,)
            const float* __restrict__ bhh,   // (204,)
            const float* __restrict__ Wfc,   // (1, 51)
            const float* __restrict__ bfc,   // (1,)
            float* __restrict__ out)         // (B, SEQ, 1)
{
    __shared__ ull   sh_h[2][NPAIR];    // 52 floats; slot 51 = pad, stays 0
    __shared__ float sh_y[2][64];       // FC partials, 64-padded with zeros

    const int tid = threadIdx.x;
    const int k   = tid >> 1;           // hidden unit 0..63 (active < 51)
    const int p   = tid & 1;            // 0 -> gates (i,f), 1 -> gates (g,o)
    const int b   = blockIdx.x;
    const bool act  = (k < H);
    const bool even = (p == 0);

    // zero shared (h0 = 0, pads = 0)
    for (int i = tid; i < 2 * NPAIR; i += TPB) ((ull*)sh_h)[i] = 0ull;
    for (int i = tid; i < 2 * 64;    i += TPB) ((float*)sh_y)[i] = 0.0f;

    // ---- per-thread weights: 2 gate rows (g0 = 2p, g1 = 2p+1) ----
    ull w0[NPAIR], w1[NPAIR];
#pragma unroll
    for (int m = 0; m < NPAIR; m++) { w0[m] = 0ull; w1[m] = 0ull; }
    ull bs = 0ull, wi = 0ull;
    float wfck = 0.0f, c = 0.0f;

    if (act) {
        const int g0 = k + (2 * p) * H;
        const int g1 = k + (2 * p + 1) * H;
        const float* r0 = Whh + (size_t)g0 * H;
        const float* r1 = Whh + (size_t)g1 * H;
#pragma unroll
        for (int m = 0; m < NPAIR - 1; m++) {
            w0[m] = pk2(r0[2 * m], r0[2 * m + 1]);
            w1[m] = pk2(r1[2 * m], r1[2 * m + 1]);
        }
        w0[NPAIR - 1] = pk2(r0[H - 1], 0.0f);
        w1[NPAIR - 1] = pk2(r1[H - 1], 0.0f);

        bs = pk2(bih[g0] + bhh[g0], bih[g1] + bhh[g1]);
        wi = pk2(Wih[g0], Wih[g1]);
        wfck = Wfc[k];
    }

    const float* xrow = x   + (size_t)b * SEQ;
    float*       orow = out + (size_t)b * SEQ;
    const float  bfcv = bfc[0];

    __syncthreads();

    float xv = xrow[0];
    for (int t = 0; t < SEQ; t++) {
        const int rb = t & 1;
        const int wb = rb ^ 1;
        const float xn = (t + 1 < SEQ) ? xrow[t + 1] : 0.0f;   // prefetch

        // x-term + bias for this thread's two gates
        const ull xx  = pk2(xv, xv);
        const float2 pre = unpk(fma2(xx, wi, bs));

        // two full 51-wide dot products (26 fma2 each, independent chains)
        const ull* hb = sh_h[rb];
        ull a0 = 0ull, a1 = 0ull;
#pragma unroll
        for (int m = 0; m < NPAIR; m++) {
            const ull hp = hb[m];          // broadcast LDS.64
            a0 = fma2(hp, w0[m], a0);
            a1 = fma2(hp, w1[m], a1);
        }
        const float2 u0 = unpk(a0), u1 = unpk(a1);
        float s0 = u0.x + u0.y + pre.x;    // even: gate i   | odd: gate g
        float s1 = u1.x + u1.y + pre.y;    // even: gate f   | odd: gate o

        // hand odd lane's (g, o) sums to the even lane (and vice versa, unused)
        const float o0 = __shfl_xor_sync(0xffffffffu, s0, 1);
        const float o1 = __shfl_xor_sync(0xffffffffu, s1, 1);

        if (even & act) {
            const float gi = sigf(s0);
            const float gf = sigf(s1);
            const float gg = tanh_fast(o0);
            const float go = sigf(o1);
            c = fmaf(gf, c, gi * gg);
            const float h = go * tanh_fast(c);
            ((float*)sh_h[wb])[k] = h;     // slot 51 stays 0
            sh_y[wb][k] = h * wfck;
        }
        __syncthreads();

        // FC reduction for this step (reads wb; next write to wb is after
        // the NEXT barrier, so no race)
        if (tid < 32) {
            float s = sh_y[wb][tid] + sh_y[wb][tid + 32];
            s += __shfl_xor_sync(0xffffffffu, s, 16);
            s += __shfl_xor_sync(0xffffffffu, s, 8);
            s += __shfl_xor_sync(0xffffffffu, s, 4);
            s += __shfl_xor_sync(0xffffffffu, s, 2);
            s += __shfl_xor_sync(0xffffffffu, s, 1);
            if (tid == 0) orow[t] = s + bfcv;
        }
        xv = xn;
    }
}

extern "C" void kernel_launch(void* const* d_in, const int* in_sizes, int n_in,
                              void* d_out, int out_size) {
    const float* x_in = (const float*)d_in[0];
    const float* Wih  = (const float*)d_in[1];
    const float* Whh  = (const float*)d_in[2];
    const float* bih  = (const float*)d_in[3];
    const float* bhh  = (const float*)d_in[4];
    const float* Wfc  = (const float*)d_in[5];
    const float* bfc  = (const float*)d_in[6];
    // d_in[7] = future (static 0) — ignored.
    float* out = (float*)d_out;

    lstm_kernel<<<BATCH, TPB>>>(x_in, Wih, Whh, bih, bhh, Wfc, bfc, out);
    (void)in_sizes; (void)n_in; (void)out_size;
}